// round 1
// baseline (speedup 1.0000x reference)
#include <cuda_runtime.h>

#define NNODES 500000
#define NRELS  16
#define DIM    128
#define BATCH  8192
#define KNB    64
#define LAM    0.7f

// Scratch (device globals: allocation-free, zero-initialized at module load).
// g_winnerp1[h] = (b+1) of the last triplet whose head_index == h, else 0.
// Entries touched are exactly the head positions, which are identical every
// replay, and reset_kernel clears exactly those entries each launch -> state
// is consistent across graph replays.
__device__ int   g_winnerp1[NNODES];
__device__ float g_newvec[BATCH * DIM];   // blended head vectors for masked winners

__global__ void reset_kernel(const int* __restrict__ head) {
    int b = blockIdx.x * blockDim.x + threadIdx.x;
    if (b < BATCH) g_winnerp1[head[b]] = 0;
}

__global__ void argmax_kernel(const int* __restrict__ head) {
    int b = blockIdx.x * blockDim.x + threadIdx.x;
    if (b < BATCH) atomicMax(&g_winnerp1[head[b]], b + 1);
}

// One block (128 threads) per triplet; only masked winners do work.
__global__ void disease_kernel(const int* __restrict__ head,
                               const int* __restrict__ rel,
                               const float* __restrict__ node_emb,
                               const int* __restrict__ local_idx_map,
                               const int* __restrict__ sim_neighbors,
                               const float* __restrict__ sim_weights,
                               const int* __restrict__ degree_table) {
    int b = blockIdx.x;
    int r = __ldg(&rel[b]);
    if (r < 2 || r > 4) return;                 // not a disease relation
    int h = __ldg(&head[b]);
    if (g_winnerp1[h] != b + 1) return;         // a later triplet overwrites this node

    __shared__ float w_s[KNB];
    __shared__ int   nb_s[KNB];

    int tid = threadIdx.x;
    int local = __ldg(&local_idx_map[h]);
    if (tid < KNB) {
        w_s[tid]  = __ldg(&sim_weights[(size_t)local * KNB + tid]);
        nb_s[tid] = __ldg(&sim_neighbors[(size_t)local * KNB + tid]);
    }
    __syncthreads();

    float acc = 0.0f;
#pragma unroll 8
    for (int k = 0; k < KNB; k++) {
        acc += w_s[k] * __ldg(&node_emb[(size_t)nb_s[k] * DIM + tid]);
    }

    int   deg = __ldg(&degree_table[local * 3 + (r - 2)]);
    float c   = LAM * expf(-LAM * (float)deg) + 0.2f;
    float oldv = __ldg(&node_emb[(size_t)h * DIM + tid]);
    g_newvec[b * DIM + tid] = c * acc + (1.0f - c) * oldv;
}

// One warp per triplet; float4 per lane (4*32 = 128 = DIM).
__global__ void score_kernel(const int* __restrict__ head,
                             const int* __restrict__ rel,
                             const int* __restrict__ tail,
                             const float* __restrict__ node_emb,
                             const float* __restrict__ rel_emb,
                             float* __restrict__ out) {
    int gtid = blockIdx.x * blockDim.x + threadIdx.x;
    int b    = gtid >> 5;
    int lane = gtid & 31;
    if (b >= BATCH) return;

    int h = __ldg(&head[b]);
    int t = __ldg(&tail[b]);
    int r = __ldg(&rel[b]);

    // Head vector: redirected to blended vec iff the winning writer was masked.
    int wp = g_winnerp1[h];
    const float* hv = &node_emb[(size_t)h * DIM];
    if (wp > 0) {
        int rb = __ldg(&rel[wp - 1]);
        if (rb >= 2 && rb <= 4) hv = &g_newvec[(wp - 1) * DIM];
    }
    // Tail vector: same redirection (tail may alias an updated head node).
    int wt = g_winnerp1[t];
    const float* tv = &node_emb[(size_t)t * DIM];
    if (wt > 0) {
        int rb = __ldg(&rel[wt - 1]);
        if (rb >= 2 && rb <= 4) tv = &g_newvec[(wt - 1) * DIM];
    }
    const float* rv = &rel_emb[(size_t)r * DIM];

    float4 a  = reinterpret_cast<const float4*>(hv)[lane];
    float4 rr = reinterpret_cast<const float4*>(rv)[lane];
    float4 tt = reinterpret_cast<const float4*>(tv)[lane];

    float s = a.x * rr.x * tt.x
            + a.y * rr.y * tt.y
            + a.z * rr.z * tt.z
            + a.w * rr.w * tt.w;

#pragma unroll
    for (int o = 16; o > 0; o >>= 1)
        s += __shfl_down_sync(0xFFFFFFFFu, s, o);

    if (lane == 0) out[b] = s;
}

extern "C" void kernel_launch(void* const* d_in, const int* in_sizes, int n_in,
                              void* d_out, int out_size) {
    const int*   head        = (const int*)  d_in[0];
    const int*   rel         = (const int*)  d_in[1];
    const int*   tail        = (const int*)  d_in[2];
    const float* node_emb    = (const float*)d_in[3];
    const float* rel_emb     = (const float*)d_in[4];
    const int*   local_idx   = (const int*)  d_in[5];
    const int*   sim_neigh   = (const int*)  d_in[6];
    const float* sim_w       = (const float*)d_in[7];
    const int*   degree_tab  = (const int*)  d_in[8];
    float*       out         = (float*)d_out;

    reset_kernel <<<(BATCH + 255) / 256, 256>>>(head);
    argmax_kernel<<<(BATCH + 255) / 256, 256>>>(head);
    disease_kernel<<<BATCH, DIM>>>(head, rel, node_emb, local_idx,
                                   sim_neigh, sim_w, degree_tab);
    score_kernel<<<(BATCH * 32 + 255) / 256, 256>>>(head, rel, tail,
                                                    node_emb, rel_emb, out);
}